// round 12
// baseline (speedup 1.0000x reference)
#include <cuda_runtime.h>
#include <cuda_fp16.h>
#include <cstdint>
#include <math.h>

#define DM    1024
#define DM3   3072
#define BATCH 4
#define SEQ   2048
#define DVAL  64
#define MTOT  (BATCH*SEQ)   // 8192

// ---------------- scratch (device globals; no allocs allowed) ----------------
__device__ __half g_Xh   [(size_t)MTOT * DM];
__device__ __half g_Wh   [(size_t)DM3 * DM];      // Wq|Wk|Wv stacked rows
__device__ __half g_Woh  [(size_t)DVAL * DM];
__device__ __half g_QKVh [(size_t)MTOT * DM3];    // Q|K|V column slabs
__device__ __half g_Ph   [(size_t)BATCH * SEQ * SEQ];
__device__ __half g_Ch   [(size_t)MTOT * DM];
__device__ float  g_P    [(size_t)BATCH * SEQ * SEQ]; // fp32 scores; later o-proj partials

// ---------------- helpers ----------------
__device__ __forceinline__ uint32_t smem_u32(const void* p) {
    uint32_t a;
    asm("{ .reg .u64 t; cvta.to.shared.u64 t, %1; cvt.u32.u64 %0, t; }" : "=r"(a) : "l"(p));
    return a;
}
#define SWZ(o) ((o) ^ (((o) >> 3) & 0x70))

#define CPA16(dst, src) \
    asm volatile("cp.async.cg.shared.global [%0], [%1], 16;" :: "r"(dst), "l"(src) : "memory")
#define CP_COMMIT() asm volatile("cp.async.commit_group;" ::: "memory")
#define CP_WAIT1()  asm volatile("cp.async.wait_group 1;" ::: "memory")

#define LDSM_X4(d0, d1, d2, d3, a) \
    asm volatile("ldmatrix.sync.aligned.m8n8.x4.shared.b16 {%0,%1,%2,%3}, [%4];" \
        : "=r"(d0), "=r"(d1), "=r"(d2), "=r"(d3) : "r"(a))
#define LDSM_X4T(d0, d1, d2, d3, a) \
    asm volatile("ldmatrix.sync.aligned.m8n8.x4.trans.shared.b16 {%0,%1,%2,%3}, [%4];" \
        : "=r"(d0), "=r"(d1), "=r"(d2), "=r"(d3) : "r"(a))

__device__ __forceinline__ void mma16(float* c, const uint32_t* a, const uint32_t* b) {
    asm volatile(
        "mma.sync.aligned.m16n8k16.row.col.f32.f16.f16.f32 "
        "{%0,%1,%2,%3}, {%4,%5,%6,%7}, {%8,%9}, {%0,%1,%2,%3};"
        : "+f"(c[0]), "+f"(c[1]), "+f"(c[2]), "+f"(c[3])
        : "r"(a[0]), "r"(a[1]), "r"(a[2]), "r"(a[3]), "r"(b[0]), "r"(b[1]));
}

// ---------------- fp16 tensor-core GEMM ----------------
// C[M,N] = A[M,K](half,k-major) * B.  TRANSB: B[N,K].  else B[K,N] (2x 64-col SW128 panels).
// MAXB: __launch_bounds__ min-blocks (2 for 128-tile, 1 for 256-tile).
// MASK: causal+scale epilogue on fp32 C; fully-masked tiles do NOTHING.
// KLIMIT: truncate K at m0+128.  HOUT: write __half C (else fp32).
template<int TILE_N, int MAXB, bool TRANSB, bool MASK, bool KLIMIT, bool HOUT>
__global__ __launch_bounds__(256, MAXB)
void mm_h(const __half* __restrict__ A, const __half* __restrict__ Bm,
          void* __restrict__ Cv, int K, int lda, int ldb, int ldc,
          long long zsA, long long zsB, long long zsC, float scale)
{
    extern __shared__ __align__(16) char smc[];
    constexpr int STAGES = 3;
    constexpr int ASTG = 128 * 128;                                 // A stage bytes
    constexpr int BSTG = TRANSB ? TILE_N * 128 : 64 * TILE_N * 2;   // NN: panels, no pad
    constexpr int WN = TILE_N / 4;
    constexpr int NF = WN / 8;

    const int tid = threadIdx.x, lane = tid & 31, wid = tid >> 5;
    const int wm = wid & 1, wn = wid >> 1;
    const int m0 = ((MASK || KLIMIT) ? (gridDim.y - 1 - blockIdx.y) : blockIdx.y) * 128;
    const int n0 = blockIdx.x * TILE_N;

    if (MASK && n0 > m0 + 127) return;

    A  += (long long)blockIdx.z * zsA;
    Bm += (long long)blockIdx.z * zsB;
    float*  Cf = (float*)Cv  + (long long)blockIdx.z * zsC;
    __half* Ch = (__half*)Cv + (long long)blockIdx.z * zsC;

    const uint32_t aB0 = smem_u32(smc);
    const uint32_t bB0 = aB0 + STAGES * ASTG;

    const int ktiles = KLIMIT ? (m0 + 128) / 64 : K / 64;

    float acc[4][NF][4];
    #pragma unroll
    for (int i = 0; i < 4; i++)
        #pragma unroll
        for (int j = 0; j < NF; j++)
            #pragma unroll
            for (int q = 0; q < 4; q++) acc[i][j][q] = 0.0f;

    auto load_stage = [&](int t, int s) {
        const int k0 = t * 64;
        #pragma unroll
        for (int j = 0; j < 4; j++) {
            int i = tid + j * 256, r = i >> 3, sg = i & 7;
            const __half* src = A + (long long)(m0 + r) * lda + k0 + sg * 8;
            CPA16(aB0 + s * ASTG + SWZ(r * 128 + sg * 16), src);
        }
        if (TRANSB) {
            #pragma unroll
            for (int j = 0; j < TILE_N * 8 / 256; j++) {
                int i = tid + j * 256, r = i >> 3, sg = i & 7;
                const __half* src = Bm + (long long)(n0 + r) * ldb + k0 + sg * 8;
                CPA16(bB0 + s * BSTG + SWZ(r * 128 + sg * 16), src);
            }
        } else {
            #pragma unroll
            for (int j = 0; j < 64 * (TILE_N / 8) / 256; j++) {
                int i = tid + j * 256, kk = i >> 4, sg = i & 15;
                int panel = sg >> 3, cl = (sg & 7) * 16;
                const __half* src = Bm + (long long)(k0 + kk) * ldb + n0 + sg * 8;
                CPA16(bB0 + s * BSTG + panel * 8192 + SWZ(kk * 128 + cl), src);
            }
        }
    };

    // prologue: stages 0,1 (one commit group each)
    #pragma unroll
    for (int s = 0; s < STAGES - 1; s++) {
        if (s < ktiles) load_stage(s, s);
        CP_COMMIT();
    }

    uint32_t af[2][4][4];
    uint32_t bf[2][NF][2];

    for (int t = 0; t < ktiles; t++) {
        CP_WAIT1();
        __syncthreads();

        // issue loads for stage t+2 into the stage computed at t-1
        const int tn = t + STAGES - 1;
        if (tn < ktiles) load_stage(tn, tn % STAGES);
        CP_COMMIT();

        const uint32_t aS = aB0 + (t % STAGES) * ASTG;
        const uint32_t bS = bB0 + (t % STAGES) * BSTG;

        auto load_frags = [&](int ks, int pb) {
            #pragma unroll
            for (int mf = 0; mf < 4; mf++) {
                int row = wm * 64 + mf * 16 + ((lane >> 3) & 1) * 8 + (lane & 7);
                uint32_t ad = aS + SWZ(row * 128 + ks * 32 + (lane >> 4) * 16);
                LDSM_X4(af[pb][mf][0], af[pb][mf][1], af[pb][mf][2], af[pb][mf][3], ad);
            }
            #pragma unroll
            for (int p = 0; p < NF / 2; p++) {
                uint32_t d0, d1, d2, d3;
                if (TRANSB) {
                    int row = wn * WN + p * 16 + (lane >> 4) * 8 + (lane & 7);
                    uint32_t bd = bS + SWZ(row * 128 + ks * 32 + ((lane >> 3) & 1) * 16);
                    LDSM_X4(d0, d1, d2, d3, bd);
                } else {
                    int kr  = ks * 16 + ((lane >> 3) & 1) * 8 + (lane & 7);
                    int col = wn * WN + p * 16 + (lane >> 4) * 8;
                    int panel = col >> 6, cl = (col & 63) * 2;
                    uint32_t bd = bS + panel * 8192 + SWZ(kr * 128 + cl);
                    LDSM_X4T(d0, d1, d2, d3, bd);
                }
                bf[pb][2 * p][0] = d0; bf[pb][2 * p][1] = d1;
                bf[pb][2 * p + 1][0] = d2; bf[pb][2 * p + 1][1] = d3;
            }
        };

        load_frags(0, 0);
        #pragma unroll
        for (int ks = 0; ks < 4; ks++) {
            const int cur = ks & 1;
            if (ks < 3) load_frags(ks + 1, cur ^ 1);   // hide LDSM under MMA
            #pragma unroll
            for (int mf = 0; mf < 4; mf++)
                #pragma unroll
                for (int nf = 0; nf < NF; nf++)
                    mma16(acc[mf][nf], af[cur][mf], bf[cur][nf]);
        }
    }

    // ---- epilogue ----
    const float ni = __int_as_float(0xff800000);
    #pragma unroll
    for (int mf = 0; mf < 4; mf++) {
        const int r0 = m0 + wm * 64 + mf * 16 + (lane >> 2);
        const int r1 = r0 + 8;
        #pragma unroll
        for (int nf = 0; nf < NF; nf++) {
            const int c = n0 + wn * WN + nf * 8 + 2 * (lane & 3);
            float2 v0 = make_float2(acc[mf][nf][0], acc[mf][nf][1]);
            float2 v1 = make_float2(acc[mf][nf][2], acc[mf][nf][3]);
            if (MASK) {
                v0.x = (c     <= r0) ? v0.x * scale : ni;
                v0.y = (c + 1 <= r0) ? v0.y * scale : ni;
                v1.x = (c     <= r1) ? v1.x * scale : ni;
                v1.y = (c + 1 <= r1) ? v1.y * scale : ni;
            }
            if (HOUT) {
                *(__half2*)&Ch[(long long)r0 * ldc + c] = __floats2half2_rn(v0.x, v0.y);
                *(__half2*)&Ch[(long long)r1 * ldc + c] = __floats2half2_rn(v1.x, v1.y);
            } else {
                *(float2*)&Cf[(long long)r0 * ldc + c] = v0;
                *(float2*)&Cf[(long long)r1 * ldc + c] = v1;
            }
        }
    }
}

// ---------------- fused fp32 -> fp16 pre-pass (single launch) ----------------
#define NX4  (MTOT * DM / 4)        // 2097152
#define NW4  (DM * DM / 4)          // 262144
#define NWO4 (DVAL * DM / 4)        // 16384
#define NALL4 (NX4 + 3 * NW4 + NWO4)

__global__ __launch_bounds__(256)
void f2h_all_kernel(const float4* __restrict__ x,  const float4* __restrict__ wq,
                    const float4* __restrict__ wk, const float4* __restrict__ wv,
                    const float4* __restrict__ wo)
{
    int i = blockIdx.x * 256 + threadIdx.x;
    const float4* src;
    __half2* dst;
    int off;
    if (i < NX4)                      { src = x;  dst = (__half2*)g_Xh;               off = i; }
    else if (i < NX4 + NW4)           { src = wq; dst = (__half2*)g_Wh;               off = i - NX4; }
    else if (i < NX4 + 2 * NW4)       { src = wk; dst = (__half2*)(g_Wh + DM * DM);   off = i - NX4 - NW4; }
    else if (i < NX4 + 3 * NW4)       { src = wv; dst = (__half2*)(g_Wh + 2 * DM * DM); off = i - NX4 - 2 * NW4; }
    else if (i < NALL4)               { src = wo; dst = (__half2*)g_Woh;              off = i - NX4 - 3 * NW4; }
    else return;
    float4 v = src[off];
    dst[2 * off]     = __floats2half2_rn(v.x, v.y);
    dst[2 * off + 1] = __floats2half2_rn(v.z, v.w);
}

// ---------------- split-K add: out = p0 + p1 (fp32) ----------------
__global__ __launch_bounds__(256)
void addk_kernel(const float4* __restrict__ p0, const float4* __restrict__ p1,
                 float4* __restrict__ out, int n4)
{
    int i = blockIdx.x * 256 + threadIdx.x;
    if (i < n4) {
        float4 a = p0[i], b = p1[i];
        out[i] = make_float4(a.x + b.x, a.y + b.y, a.z + b.z, a.w + b.w);
    }
}

// ---------------- causal softmax: warp-per-row, all-register ----------------
__global__ __launch_bounds__(256)
void softmax_kernel()
{
    const int gw   = blockIdx.x * 8 + (threadIdx.x >> 5);
    const int lane = threadIdx.x & 31;
    const long long row = MTOT - 1 - gw;          // heavy rows first
    const int r  = (int)(row & (SEQ - 1));
    const int C4 = ((r | 127) + 1) >> 2;
    const float4* p4 = (const float4*)(g_P + row * SEQ);
    __half2* o2 = (__half2*)(g_Ph + row * SEQ);

    float4 v[16];
    float m = __int_as_float(0xff800000);
    #pragma unroll
    for (int j = 0; j < 16; j++) {
        int i = lane + j * 32;
        if (i < C4) {
            v[j] = p4[i];
            m = fmaxf(m, fmaxf(fmaxf(v[j].x, v[j].y), fmaxf(v[j].z, v[j].w)));
        }
    }
    #pragma unroll
    for (int off = 16; off > 0; off >>= 1)
        m = fmaxf(m, __shfl_xor_sync(0xffffffffu, m, off));

    float sum = 0.0f;
    #pragma unroll
    for (int j = 0; j < 16; j++) {
        int i = lane + j * 32;
        if (i < C4) {
            v[j].x = __expf(v[j].x - m); v[j].y = __expf(v[j].y - m);
            v[j].z = __expf(v[j].z - m); v[j].w = __expf(v[j].w - m);
            sum += (v[j].x + v[j].y) + (v[j].z + v[j].w);
        }
    }
    #pragma unroll
    for (int off = 16; off > 0; off >>= 1)
        sum += __shfl_xor_sync(0xffffffffu, sum, off);
    const float inv = 1.0f / sum;

    #pragma unroll
    for (int j = 0; j < 16; j++) {
        int i = lane + j * 32;
        if (i < C4) {
            o2[2 * i]     = __floats2half2_rn(v[j].x * inv, v[j].y * inv);
            o2[2 * i + 1] = __floats2half2_rn(v[j].z * inv, v[j].w * inv);
        }
    }
}

// ---------------- host ----------------
extern "C" void kernel_launch(void* const* d_in, const int* in_sizes, int n_in,
                              void* d_out, int out_size)
{
    const float* x  = (const float*)d_in[0];
    const float* Wq = (const float*)d_in[1];
    const float* Wk = (const float*)d_in[2];
    const float* Wv = (const float*)d_in[3];
    const float* Wo = (const float*)d_in[4];
    float* out = (float*)d_out;

    __half *Xh, *Wh, *Woh, *QKVh, *Ph, *Chx;
    float* P;
    cudaGetSymbolAddress((void**)&Xh,   g_Xh);
    cudaGetSymbolAddress((void**)&Wh,   g_Wh);
    cudaGetSymbolAddress((void**)&Woh,  g_Woh);
    cudaGetSymbolAddress((void**)&QKVh, g_QKVh);
    cudaGetSymbolAddress((void**)&Ph,   g_Ph);
    cudaGetSymbolAddress((void**)&Chx,  g_Ch);
    cudaGetSymbolAddress((void**)&P,    g_P);

    const __half* Qh = QKVh;
    const __half* Kh = QKVh + DM;
    const __half* Vh = QKVh + 2 * DM;

    float* op0 = P;                         // o-proj partials reuse g_P
    float* op1 = P + (size_t)MTOT * DVAL;

    const int smNT256 = 3 * (16384 + 256 * 128);    // 144KB (QKV, occ 1)
    const int smNT128 = 3 * (16384 + 128 * 128);    // 96KB
    const int smNN128 = 3 * (16384 + 64 * 128 * 2); // 96KB
    const int smNT64  = 3 * (16384 + 64 * 128);     // 72KB
    cudaFuncSetAttribute(mm_h<256, 1, true,  false, false, true >, cudaFuncAttributeMaxDynamicSharedMemorySize, smNT256);
    cudaFuncSetAttribute(mm_h<128, 2, true,  true,  false, false>, cudaFuncAttributeMaxDynamicSharedMemorySize, smNT128);
    cudaFuncSetAttribute(mm_h<128, 2, false, false, true,  true >, cudaFuncAttributeMaxDynamicSharedMemorySize, smNN128);
    cudaFuncSetAttribute(mm_h<64,  2, true,  false, false, false>, cudaFuncAttributeMaxDynamicSharedMemorySize, smNT64);

    const dim3 blk(256);
    const float scale = 1.0f / 32.0f;   // 1/sqrt(1024)

    // 0) fused fp32->fp16 prepass (one launch)
    f2h_all_kernel<<<(NALL4 + 255) / 256, 256>>>(
        (const float4*)x, (const float4*)Wq, (const float4*)Wk,
        (const float4*)Wv, (const float4*)Wo);

    // 1) fused QKV projection: [8192,3072] = X @ [Wq|Wk|Wv]^T  (NT, 128x256 tiles, occ1)
    mm_h<256, 1, true, false, false, true><<<dim3(DM3 / 256, MTOT / 128, 1), blk, smNT256>>>(
        Xh, Wh, QKVh, DM, DM, DM, DM3, 0, 0, 0, 1.0f);

    // 2) scores = mask(Q @ K^T) * scale  (NT + causal, fp32 out)
    mm_h<128, 2, true, true, false, false><<<dim3(SEQ / 128, SEQ / 128, BATCH), blk, smNT128>>>(
        Qh, Kh, P, DM, DM3, DM3, SEQ,
        (long long)SEQ * DM3, (long long)SEQ * DM3, (long long)SEQ * SEQ, scale);

    // 3) causal softmax: warp-per-row, fp32 scores -> fp16 probs
    softmax_kernel<<<MTOT / 8, 256>>>();

    // 4) ctx = P @ V  (NN + causal k-limit, half out)
    mm_h<128, 2, false, false, true, true><<<dim3(DM / 128, SEQ / 128, BATCH), blk, smNN128>>>(
        Ph, Vh, Chx, SEQ, SEQ, DM3, DM,
        (long long)SEQ * SEQ, (long long)SEQ * DM3, (long long)SEQ * DM, 1.0f);

    // 5) out = ctx @ Wo^T  (NT, fp32), 2-way split-K
    mm_h<64, 2, true, false, false, false><<<dim3(DVAL / 64, MTOT / 128, 1), blk, smNT64>>>(
        Chx, Woh, op0, 512, DM, DM, DVAL, 0, 0, 0, 1.0f);
    mm_h<64, 2, true, false, false, false><<<dim3(DVAL / 64, MTOT / 128, 1), blk, smNT64>>>(
        Chx + 512, Woh + 512, op1, 512, DM, DM, DVAL, 0, 0, 0, 1.0f);
    addk_kernel<<<(MTOT * DVAL / 4 + 255) / 256, 256>>>(
        (const float4*)op0, (const float4*)op1, (float4*)out, MTOT * DVAL / 4);
}

// round 13
// speedup vs baseline: 1.0904x; 1.0904x over previous
#include <cuda_runtime.h>
#include <cuda_fp16.h>
#include <cstdint>
#include <math.h>

#define DM    1024
#define DM3   3072
#define BATCH 4
#define SEQ   2048
#define DVAL  64
#define MTOT  (BATCH*SEQ)   // 8192

// ---------------- scratch (device globals; no allocs allowed) ----------------
__device__ __half g_Xh   [(size_t)MTOT * DM];
__device__ __half g_Wh   [(size_t)DM3 * DM];      // Wq|Wk|Wv stacked rows
__device__ __half g_Woh  [(size_t)DVAL * DM];
__device__ __half g_QKVh [(size_t)MTOT * DM3];    // Q|K|V column slabs
__device__ __half g_Ph   [(size_t)BATCH * SEQ * SEQ];
__device__ __half g_Ch   [(size_t)MTOT * DM];
__device__ float  g_P    [(size_t)BATCH * SEQ * SEQ]; // fp32 scores; later o-proj partials

// ---------------- helpers ----------------
__device__ __forceinline__ uint32_t smem_u32(const void* p) {
    uint32_t a;
    asm("{ .reg .u64 t; cvta.to.shared.u64 t, %1; cvt.u32.u64 %0, t; }" : "=r"(a) : "l"(p));
    return a;
}
#define SWZ(o) ((o) ^ (((o) >> 3) & 0x70))

#define CPA16(dst, src) \
    asm volatile("cp.async.cg.shared.global [%0], [%1], 16;" :: "r"(dst), "l"(src) : "memory")
#define CP_COMMIT() asm volatile("cp.async.commit_group;" ::: "memory")
#define CP_WAIT1()  asm volatile("cp.async.wait_group 1;" ::: "memory")

#define LDSM_X4(d0, d1, d2, d3, a) \
    asm volatile("ldmatrix.sync.aligned.m8n8.x4.shared.b16 {%0,%1,%2,%3}, [%4];" \
        : "=r"(d0), "=r"(d1), "=r"(d2), "=r"(d3) : "r"(a))
#define LDSM_X4T(d0, d1, d2, d3, a) \
    asm volatile("ldmatrix.sync.aligned.m8n8.x4.trans.shared.b16 {%0,%1,%2,%3}, [%4];" \
        : "=r"(d0), "=r"(d1), "=r"(d2), "=r"(d3) : "r"(a))

__device__ __forceinline__ void mma16(float* c, const uint32_t* a, const uint32_t* b) {
    asm volatile(
        "mma.sync.aligned.m16n8k16.row.col.f32.f16.f16.f32 "
        "{%0,%1,%2,%3}, {%4,%5,%6,%7}, {%8,%9}, {%0,%1,%2,%3};"
        : "+f"(c[0]), "+f"(c[1]), "+f"(c[2]), "+f"(c[3])
        : "r"(a[0]), "r"(a[1]), "r"(a[2]), "r"(a[3]), "r"(b[0]), "r"(b[1]));
}

// ---------------- fp16 tensor-core GEMM (128x128, occ 2) ----------------
// C[M,N] = A[M,K](half,k-major) * B.  TRANSB: B[N,K].  else B[K,N] (2x 64-col SW128 panels).
// MASK: causal+scale epilogue on fp32 C; fully-masked tiles do NOTHING.
// KLIMIT: truncate K at m0+128.  HOUT: write __half C (else fp32).
// MASK/KLIMIT kernels map blockIdx.y in REVERSE so heavy tiles launch first.
template<int TILE_N, bool TRANSB, bool MASK, bool KLIMIT, bool HOUT>
__global__ __launch_bounds__(256, 2)
void mm_h(const __half* __restrict__ A, const __half* __restrict__ Bm,
          void* __restrict__ Cv, int K, int lda, int ldb, int ldc,
          long long zsA, long long zsB, long long zsC, float scale)
{
    extern __shared__ __align__(16) char smc[];
    constexpr int STAGES = 3;
    constexpr int ASTG = 128 * 128;                                 // A stage bytes
    constexpr int BSTG = TRANSB ? TILE_N * 128 : 64 * TILE_N * 2;   // NN: panels, no pad
    constexpr int WN = TILE_N / 4;
    constexpr int NF = WN / 8;

    const int tid = threadIdx.x, lane = tid & 31, wid = tid >> 5;
    const int wm = wid & 1, wn = wid >> 1;
    const int m0 = ((MASK || KLIMIT) ? (gridDim.y - 1 - blockIdx.y) : blockIdx.y) * 128;
    const int n0 = blockIdx.x * TILE_N;

    if (MASK && n0 > m0 + 127) return;

    A  += (long long)blockIdx.z * zsA;
    Bm += (long long)blockIdx.z * zsB;
    float*  Cf = (float*)Cv  + (long long)blockIdx.z * zsC;
    __half* Ch = (__half*)Cv + (long long)blockIdx.z * zsC;

    const uint32_t aB0 = smem_u32(smc);
    const uint32_t bB0 = aB0 + STAGES * ASTG;

    const int ktiles = KLIMIT ? (m0 + 128) / 64 : K / 64;

    float acc[4][NF][4];
    #pragma unroll
    for (int i = 0; i < 4; i++)
        #pragma unroll
        for (int j = 0; j < NF; j++)
            #pragma unroll
            for (int q = 0; q < 4; q++) acc[i][j][q] = 0.0f;

    auto load_stage = [&](int t, int s) {
        const int k0 = t * 64;
        #pragma unroll
        for (int j = 0; j < 4; j++) {
            int i = tid + j * 256, r = i >> 3, sg = i & 7;
            const __half* src = A + (long long)(m0 + r) * lda + k0 + sg * 8;
            CPA16(aB0 + s * ASTG + SWZ(r * 128 + sg * 16), src);
        }
        if (TRANSB) {
            #pragma unroll
            for (int j = 0; j < TILE_N * 8 / 256; j++) {
                int i = tid + j * 256, r = i >> 3, sg = i & 7;
                const __half* src = Bm + (long long)(n0 + r) * ldb + k0 + sg * 8;
                CPA16(bB0 + s * BSTG + SWZ(r * 128 + sg * 16), src);
            }
        } else {
            #pragma unroll
            for (int j = 0; j < 64 * (TILE_N / 8) / 256; j++) {
                int i = tid + j * 256, kk = i >> 4, sg = i & 15;
                int panel = sg >> 3, cl = (sg & 7) * 16;
                const __half* src = Bm + (long long)(k0 + kk) * ldb + n0 + sg * 8;
                CPA16(bB0 + s * BSTG + panel * 8192 + SWZ(kk * 128 + cl), src);
            }
        }
    };

    // prologue: stages 0,1 (one commit group each)
    #pragma unroll
    for (int s = 0; s < STAGES - 1; s++) {
        if (s < ktiles) load_stage(s, s);
        CP_COMMIT();
    }

    uint32_t af[2][4][4];
    uint32_t bf[2][NF][2];

    for (int t = 0; t < ktiles; t++) {
        CP_WAIT1();
        __syncthreads();

        // issue loads for stage t+2 into the stage computed at t-1
        const int tn = t + STAGES - 1;
        if (tn < ktiles) load_stage(tn, tn % STAGES);
        CP_COMMIT();

        const uint32_t aS = aB0 + (t % STAGES) * ASTG;
        const uint32_t bS = bB0 + (t % STAGES) * BSTG;

        auto load_frags = [&](int ks, int pb) {
            #pragma unroll
            for (int mf = 0; mf < 4; mf++) {
                int row = wm * 64 + mf * 16 + ((lane >> 3) & 1) * 8 + (lane & 7);
                uint32_t ad = aS + SWZ(row * 128 + ks * 32 + (lane >> 4) * 16);
                LDSM_X4(af[pb][mf][0], af[pb][mf][1], af[pb][mf][2], af[pb][mf][3], ad);
            }
            #pragma unroll
            for (int p = 0; p < NF / 2; p++) {
                uint32_t d0, d1, d2, d3;
                if (TRANSB) {
                    int row = wn * WN + p * 16 + (lane >> 4) * 8 + (lane & 7);
                    uint32_t bd = bS + SWZ(row * 128 + ks * 32 + ((lane >> 3) & 1) * 16);
                    LDSM_X4(d0, d1, d2, d3, bd);
                } else {
                    int kr  = ks * 16 + ((lane >> 3) & 1) * 8 + (lane & 7);
                    int col = wn * WN + p * 16 + (lane >> 4) * 8;
                    int panel = col >> 6, cl = (col & 63) * 2;
                    uint32_t bd = bS + panel * 8192 + SWZ(kr * 128 + cl);
                    LDSM_X4T(d0, d1, d2, d3, bd);
                }
                bf[pb][2 * p][0] = d0; bf[pb][2 * p][1] = d1;
                bf[pb][2 * p + 1][0] = d2; bf[pb][2 * p + 1][1] = d3;
            }
        };

        load_frags(0, 0);
        #pragma unroll
        for (int ks = 0; ks < 4; ks++) {
            const int cur = ks & 1;
            if (ks < 3) load_frags(ks + 1, cur ^ 1);   // hide LDSM under MMA
            #pragma unroll
            for (int mf = 0; mf < 4; mf++)
                #pragma unroll
                for (int nf = 0; nf < NF; nf++)
                    mma16(acc[mf][nf], af[cur][mf], bf[cur][nf]);
        }
    }

    // ---- epilogue ----
    const float ni = __int_as_float(0xff800000);
    #pragma unroll
    for (int mf = 0; mf < 4; mf++) {
        const int r0 = m0 + wm * 64 + mf * 16 + (lane >> 2);
        const int r1 = r0 + 8;
        #pragma unroll
        for (int nf = 0; nf < NF; nf++) {
            const int c = n0 + wn * WN + nf * 8 + 2 * (lane & 3);
            float2 v0 = make_float2(acc[mf][nf][0], acc[mf][nf][1]);
            float2 v1 = make_float2(acc[mf][nf][2], acc[mf][nf][3]);
            if (MASK) {
                v0.x = (c     <= r0) ? v0.x * scale : ni;
                v0.y = (c + 1 <= r0) ? v0.y * scale : ni;
                v1.x = (c     <= r1) ? v1.x * scale : ni;
                v1.y = (c + 1 <= r1) ? v1.y * scale : ni;
            }
            if (HOUT) {
                *(__half2*)&Ch[(long long)r0 * ldc + c] = __floats2half2_rn(v0.x, v0.y);
                *(__half2*)&Ch[(long long)r1 * ldc + c] = __floats2half2_rn(v1.x, v1.y);
            } else {
                *(float2*)&Cf[(long long)r0 * ldc + c] = v0;
                *(float2*)&Cf[(long long)r1 * ldc + c] = v1;
            }
        }
    }
}

// ---------------- fused fp32 -> fp16 pre-pass (single launch) ----------------
#define NX4  (MTOT * DM / 4)        // 2097152
#define NW4  (DM * DM / 4)          // 262144
#define NWO4 (DVAL * DM / 4)        // 16384
#define NALL4 (NX4 + 3 * NW4 + NWO4)

__global__ __launch_bounds__(256)
void f2h_all_kernel(const float4* __restrict__ x,  const float4* __restrict__ wq,
                    const float4* __restrict__ wk, const float4* __restrict__ wv,
                    const float4* __restrict__ wo)
{
    int i = blockIdx.x * 256 + threadIdx.x;
    const float4* src;
    __half2* dst;
    int off;
    if (i < NX4)                      { src = x;  dst = (__half2*)g_Xh;                 off = i; }
    else if (i < NX4 + NW4)           { src = wq; dst = (__half2*)g_Wh;                 off = i - NX4; }
    else if (i < NX4 + 2 * NW4)       { src = wk; dst = (__half2*)(g_Wh + DM * DM);     off = i - NX4 - NW4; }
    else if (i < NX4 + 3 * NW4)       { src = wv; dst = (__half2*)(g_Wh + 2 * DM * DM); off = i - NX4 - 2 * NW4; }
    else if (i < NALL4)               { src = wo; dst = (__half2*)g_Woh;                off = i - NX4 - 3 * NW4; }
    else return;
    float4 v = src[off];
    dst[2 * off]     = __floats2half2_rn(v.x, v.y);
    dst[2 * off + 1] = __floats2half2_rn(v.z, v.w);
}

// ---------------- split-K add: out = p0 + p1 (fp32) ----------------
__global__ __launch_bounds__(256)
void addk_kernel(const float4* __restrict__ p0, const float4* __restrict__ p1,
                 float4* __restrict__ out, int n4)
{
    int i = blockIdx.x * 256 + threadIdx.x;
    if (i < n4) {
        float4 a = p0[i], b = p1[i];
        out[i] = make_float4(a.x + b.x, a.y + b.y, a.z + b.z, a.w + b.w);
    }
}

// ---------------- causal softmax: warp-per-row, all-register ----------------
__global__ __launch_bounds__(256)
void softmax_kernel()
{
    const int gw   = blockIdx.x * 8 + (threadIdx.x >> 5);
    const int lane = threadIdx.x & 31;
    const long long row = MTOT - 1 - gw;          // heavy rows first
    const int r  = (int)(row & (SEQ - 1));
    const int C4 = ((r | 127) + 1) >> 2;
    const float4* p4 = (const float4*)(g_P + row * SEQ);
    __half2* o2 = (__half2*)(g_Ph + row * SEQ);

    float4 v[16];
    float m = __int_as_float(0xff800000);
    #pragma unroll
    for (int j = 0; j < 16; j++) {
        int i = lane + j * 32;
        if (i < C4) {
            v[j] = p4[i];
            m = fmaxf(m, fmaxf(fmaxf(v[j].x, v[j].y), fmaxf(v[j].z, v[j].w)));
        }
    }
    #pragma unroll
    for (int off = 16; off > 0; off >>= 1)
        m = fmaxf(m, __shfl_xor_sync(0xffffffffu, m, off));

    float sum = 0.0f;
    #pragma unroll
    for (int j = 0; j < 16; j++) {
        int i = lane + j * 32;
        if (i < C4) {
            v[j].x = __expf(v[j].x - m); v[j].y = __expf(v[j].y - m);
            v[j].z = __expf(v[j].z - m); v[j].w = __expf(v[j].w - m);
            sum += (v[j].x + v[j].y) + (v[j].z + v[j].w);
        }
    }
    #pragma unroll
    for (int off = 16; off > 0; off >>= 1)
        sum += __shfl_xor_sync(0xffffffffu, sum, off);
    const float inv = 1.0f / sum;

    #pragma unroll
    for (int j = 0; j < 16; j++) {
        int i = lane + j * 32;
        if (i < C4) {
            o2[2 * i]     = __floats2half2_rn(v[j].x * inv, v[j].y * inv);
            o2[2 * i + 1] = __floats2half2_rn(v[j].z * inv, v[j].w * inv);
        }
    }
}

// ---------------- host ----------------
extern "C" void kernel_launch(void* const* d_in, const int* in_sizes, int n_in,
                              void* d_out, int out_size)
{
    const float* x  = (const float*)d_in[0];
    const float* Wq = (const float*)d_in[1];
    const float* Wk = (const float*)d_in[2];
    const float* Wv = (const float*)d_in[3];
    const float* Wo = (const float*)d_in[4];
    float* out = (float*)d_out;

    __half *Xh, *Wh, *Woh, *QKVh, *Ph, *Chx;
    float* P;
    cudaGetSymbolAddress((void**)&Xh,   g_Xh);
    cudaGetSymbolAddress((void**)&Wh,   g_Wh);
    cudaGetSymbolAddress((void**)&Woh,  g_Woh);
    cudaGetSymbolAddress((void**)&QKVh, g_QKVh);
    cudaGetSymbolAddress((void**)&Ph,   g_Ph);
    cudaGetSymbolAddress((void**)&Chx,  g_Ch);
    cudaGetSymbolAddress((void**)&P,    g_P);

    const __half* Qh = QKVh;
    const __half* Kh = QKVh + DM;
    const __half* Vh = QKVh + 2 * DM;

    float* op0 = P;                         // o-proj partials reuse g_P
    float* op1 = P + (size_t)MTOT * DVAL;

    const int smNT128 = 3 * (16384 + 128 * 128);    // 96KB
    const int smNN128 = 3 * (16384 + 64 * 128 * 2); // 96KB
    const int smNT64  = 3 * (16384 + 64 * 128);     // 72KB
    cudaFuncSetAttribute(mm_h<128, true,  false, false, true >, cudaFuncAttributeMaxDynamicSharedMemorySize, smNT128);
    cudaFuncSetAttribute(mm_h<128, true,  true,  false, false>, cudaFuncAttributeMaxDynamicSharedMemorySize, smNT128);
    cudaFuncSetAttribute(mm_h<128, false, false, true,  true >, cudaFuncAttributeMaxDynamicSharedMemorySize, smNN128);
    cudaFuncSetAttribute(mm_h<64,  true,  false, false, false>, cudaFuncAttributeMaxDynamicSharedMemorySize, smNT64);

    const dim3 blk(256);
    const float scale = 1.0f / 32.0f;   // 1/sqrt(1024)

    // 0) fused fp32->fp16 prepass (one launch)
    f2h_all_kernel<<<(NALL4 + 255) / 256, 256>>>(
        (const float4*)x, (const float4*)Wq, (const float4*)Wk,
        (const float4*)Wv, (const float4*)Wo);

    // 1) fused QKV projection: [8192,3072] = X @ [Wq|Wk|Wv]^T  (NT, 128x128, occ2)
    mm_h<128, true, false, false, true><<<dim3(DM3 / 128, MTOT / 128, 1), blk, smNT128>>>(
        Xh, Wh, QKVh, DM, DM, DM, DM3, 0, 0, 0, 1.0f);

    // 2) scores = mask(Q @ K^T) * scale  (NT + causal, fp32 out, heavy-first)
    mm_h<128, true, true, false, false><<<dim3(SEQ / 128, SEQ / 128, BATCH), blk, smNT128>>>(
        Qh, Kh, P, DM, DM3, DM3, SEQ,
        (long long)SEQ * DM3, (long long)SEQ * DM3, (long long)SEQ * SEQ, scale);

    // 3) causal softmax: warp-per-row, fp32 scores -> fp16 probs
    softmax_kernel<<<MTOT / 8, 256>>>();

    // 4) ctx = P @ V  (NN + causal k-limit, half out, heavy-first)
    mm_h<128, false, false, true, true><<<dim3(DM / 128, SEQ / 128, BATCH), blk, smNN128>>>(
        Ph, Vh, Chx, SEQ, SEQ, DM3, DM,
        (long long)SEQ * SEQ, (long long)SEQ * DM3, (long long)SEQ * DM, 1.0f);

    // 5) out = ctx @ Wo^T  (NT, fp32), 2-way split-K in ONE launch (z = K-half)
    mm_h<64, true, false, false, false><<<dim3(DVAL / 64, MTOT / 128, 2), blk, smNT64>>>(
        Chx, Woh, op0, 512, DM, DM, DVAL,
        512, 512, (long long)MTOT * DVAL, 1.0f);
    addk_kernel<<<(MTOT * DVAL / 4 + 255) / 256, 256>>>(
        (const float4*)op0, (const float4*)op1, (float4*)out, MTOT * DVAL / 4);
}

// round 14
// speedup vs baseline: 1.2208x; 1.1196x over previous
#include <cuda_runtime.h>
#include <cuda_fp16.h>
#include <cstdint>
#include <math.h>

#define DM    1024
#define DM3   3072
#define BATCH 4
#define SEQ   2048
#define DVAL  64
#define MTOT  (BATCH*SEQ)   // 8192

// ---------------- scratch (device globals; no allocs allowed) ----------------
__device__ __half g_Xh   [(size_t)MTOT * DM];
__device__ __half g_Wh   [(size_t)DM3 * DM];      // Wq|Wk|Wv stacked rows
__device__ __half g_Woh  [(size_t)DVAL * DM];
__device__ __half g_QKVh [(size_t)MTOT * DM3];    // Q|K|V column slabs
__device__ __half g_Ph   [(size_t)BATCH * SEQ * SEQ];
__device__ __half g_Ch   [(size_t)MTOT * DM];
__device__ float  g_P    [(size_t)BATCH * SEQ * SEQ]; // fp32 scores; later o-proj partials

// ---------------- helpers ----------------
__device__ __forceinline__ uint32_t smem_u32(const void* p) {
    uint32_t a;
    asm("{ .reg .u64 t; cvta.to.shared.u64 t, %1; cvt.u32.u64 %0, t; }" : "=r"(a) : "l"(p));
    return a;
}
#define SWZ(o) ((o) ^ (((o) >> 3) & 0x70))

#define CPA16(dst, src) \
    asm volatile("cp.async.cg.shared.global [%0], [%1], 16;" :: "r"(dst), "l"(src) : "memory")
#define CP_COMMIT() asm volatile("cp.async.commit_group;" ::: "memory")
#define CP_WAIT1()  asm volatile("cp.async.wait_group 1;" ::: "memory")

#define LDSM_X4(d0, d1, d2, d3, a) \
    asm volatile("ldmatrix.sync.aligned.m8n8.x4.shared.b16 {%0,%1,%2,%3}, [%4];" \
        : "=r"(d0), "=r"(d1), "=r"(d2), "=r"(d3) : "r"(a))
#define LDSM_X4T(d0, d1, d2, d3, a) \
    asm volatile("ldmatrix.sync.aligned.m8n8.x4.trans.shared.b16 {%0,%1,%2,%3}, [%4];" \
        : "=r"(d0), "=r"(d1), "=r"(d2), "=r"(d3) : "r"(a))

__device__ __forceinline__ void mma16(float* c, const uint32_t* a, const uint32_t* b) {
    asm volatile(
        "mma.sync.aligned.m16n8k16.row.col.f32.f16.f16.f32 "
        "{%0,%1,%2,%3}, {%4,%5,%6,%7}, {%8,%9}, {%0,%1,%2,%3};"
        : "+f"(c[0]), "+f"(c[1]), "+f"(c[2]), "+f"(c[3])
        : "r"(a[0]), "r"(a[1]), "r"(a[2]), "r"(a[3]), "r"(b[0]), "r"(b[1]));
}

// ---------------- shared GEMM body (128-row tiles, BK=64, 3-stage, occ 2) ----
// C[m0:+128, n0:+TILE_N] = A[*,K] * B.  TRANSB: B[N,K] NT.  else B[K,N] (64-col SW128 panels).
// Runtime: ktiles, mask(causal+scale epilogue), hout(half vs float C).
template<int TILE_N, bool TRANSB>
__device__ __forceinline__ void gemm_body(
    const __half* __restrict__ A, const __half* __restrict__ Bm, void* __restrict__ Cv,
    int ktiles, int lda, int ldb, int ldc, int m0, int n0,
    bool mask, bool hout, float scale)
{
    extern __shared__ __align__(16) char smc[];
    constexpr int STAGES = 3;
    constexpr int ASTG = 128 * 128;                                 // A stage bytes
    constexpr int BSTG = TRANSB ? TILE_N * 128 : 64 * TILE_N * 2;   // NN: panels, no pad
    constexpr int WN = TILE_N / 4;
    constexpr int NF = WN / 8;

    const int tid = threadIdx.x, lane = tid & 31, wid = tid >> 5;
    const int wm = wid & 1, wn = wid >> 1;

    float*  Cf = (float*)Cv;
    __half* Ch = (__half*)Cv;

    const uint32_t aB0 = smem_u32(smc);
    const uint32_t bB0 = aB0 + STAGES * ASTG;

    float acc[4][NF][4];
    #pragma unroll
    for (int i = 0; i < 4; i++)
        #pragma unroll
        for (int j = 0; j < NF; j++)
            #pragma unroll
            for (int q = 0; q < 4; q++) acc[i][j][q] = 0.0f;

    auto load_stage = [&](int t, int s) {
        const int k0 = t * 64;
        #pragma unroll
        for (int j = 0; j < 4; j++) {
            int i = tid + j * 256, r = i >> 3, sg = i & 7;
            const __half* src = A + (long long)(m0 + r) * lda + k0 + sg * 8;
            CPA16(aB0 + s * ASTG + SWZ(r * 128 + sg * 16), src);
        }
        if (TRANSB) {
            #pragma unroll
            for (int j = 0; j < TILE_N * 8 / 256; j++) {
                int i = tid + j * 256, r = i >> 3, sg = i & 7;
                const __half* src = Bm + (long long)(n0 + r) * ldb + k0 + sg * 8;
                CPA16(bB0 + s * BSTG + SWZ(r * 128 + sg * 16), src);
            }
        } else {
            #pragma unroll
            for (int j = 0; j < 64 * (TILE_N / 8) / 256; j++) {
                int i = tid + j * 256, kk = i >> 4, sg = i & 15;
                int panel = sg >> 3, cl = (sg & 7) * 16;
                const __half* src = Bm + (long long)(k0 + kk) * ldb + n0 + sg * 8;
                CPA16(bB0 + s * BSTG + panel * 8192 + SWZ(kk * 128 + cl), src);
            }
        }
    };

    // prologue: stages 0,1 (one commit group each)
    #pragma unroll
    for (int s = 0; s < STAGES - 1; s++) {
        if (s < ktiles) load_stage(s, s);
        CP_COMMIT();
    }

    uint32_t af[2][4][4];
    uint32_t bf[2][NF][2];

    for (int t = 0; t < ktiles; t++) {
        CP_WAIT1();
        __syncthreads();

        const int tn = t + STAGES - 1;
        if (tn < ktiles) load_stage(tn, tn % STAGES);
        CP_COMMIT();

        const uint32_t aS = aB0 + (t % STAGES) * ASTG;
        const uint32_t bS = bB0 + (t % STAGES) * BSTG;

        auto load_frags = [&](int ks, int pb) {
            #pragma unroll
            for (int mf = 0; mf < 4; mf++) {
                int row = wm * 64 + mf * 16 + ((lane >> 3) & 1) * 8 + (lane & 7);
                uint32_t ad = aS + SWZ(row * 128 + ks * 32 + (lane >> 4) * 16);
                LDSM_X4(af[pb][mf][0], af[pb][mf][1], af[pb][mf][2], af[pb][mf][3], ad);
            }
            #pragma unroll
            for (int p = 0; p < NF / 2; p++) {
                uint32_t d0, d1, d2, d3;
                if (TRANSB) {
                    int row = wn * WN + p * 16 + (lane >> 4) * 8 + (lane & 7);
                    uint32_t bd = bS + SWZ(row * 128 + ks * 32 + ((lane >> 3) & 1) * 16);
                    LDSM_X4(d0, d1, d2, d3, bd);
                } else {
                    int kr  = ks * 16 + ((lane >> 3) & 1) * 8 + (lane & 7);
                    int col = wn * WN + p * 16 + (lane >> 4) * 8;
                    int panel = col >> 6, cl = (col & 63) * 2;
                    uint32_t bd = bS + panel * 8192 + SWZ(kr * 128 + cl);
                    LDSM_X4T(d0, d1, d2, d3, bd);
                }
                bf[pb][2 * p][0] = d0; bf[pb][2 * p][1] = d1;
                bf[pb][2 * p + 1][0] = d2; bf[pb][2 * p + 1][1] = d3;
            }
        };

        load_frags(0, 0);
        #pragma unroll
        for (int ks = 0; ks < 4; ks++) {
            const int cur = ks & 1;
            if (ks < 3) load_frags(ks + 1, cur ^ 1);   // hide LDSM under MMA
            #pragma unroll
            for (int mf = 0; mf < 4; mf++)
                #pragma unroll
                for (int nf = 0; nf < NF; nf++)
                    mma16(acc[mf][nf], af[cur][mf], bf[cur][nf]);
        }
    }

    // ---- epilogue ----
    const float ni = __int_as_float(0xff800000);
    #pragma unroll
    for (int mf = 0; mf < 4; mf++) {
        const int r0 = m0 + wm * 64 + mf * 16 + (lane >> 2);
        const int r1 = r0 + 8;
        #pragma unroll
        for (int nf = 0; nf < NF; nf++) {
            const int c = n0 + wn * WN + nf * 8 + 2 * (lane & 3);
            float2 v0 = make_float2(acc[mf][nf][0], acc[mf][nf][1]);
            float2 v1 = make_float2(acc[mf][nf][2], acc[mf][nf][3]);
            if (mask) {
                v0.x = (c     <= r0) ? v0.x * scale : ni;
                v0.y = (c + 1 <= r0) ? v0.y * scale : ni;
                v1.x = (c     <= r1) ? v1.x * scale : ni;
                v1.y = (c + 1 <= r1) ? v1.y * scale : ni;
            }
            if (hout) {
                *(__half2*)&Ch[(long long)r0 * ldc + c] = __floats2half2_rn(v0.x, v0.y);
                *(__half2*)&Ch[(long long)r1 * ldc + c] = __floats2half2_rn(v1.x, v1.y);
            } else {
                *(float2*)&Cf[(long long)r0 * ldc + c] = v0;
                *(float2*)&Cf[(long long)r1 * ldc + c] = v1;
            }
        }
    }
}

// ---------------- kernels ----------------
// 1) QK projection: [8192, 2048] = X @ [Wq|Wk]^T  (half out)
__global__ __launch_bounds__(256, 2)
void qk_kernel()
{
    gemm_body<128, true>(g_Xh, g_Wh, g_QKVh,
                         16, DM, DM, DM3,
                         blockIdx.y * 128, blockIdx.x * 128,
                         false, true, 1.0f);
}

// 2) fused: causal scores (z<4) + V projection (z=4,5) in ONE launch.
__global__ __launch_bounds__(256, 2)
void scores_v_kernel()
{
    const int z = blockIdx.z;
    const __half *Ap, *Bp;
    void* Cp;
    int lda, ldb, ldc, m0, n0;
    bool mask;
    float sc;
    if (z < BATCH) {
        m0 = (int)(15 - blockIdx.y) * 128;      // heavy tiles first
        n0 = (int)blockIdx.x * 128;
        if (n0 > m0 + 127) return;              // fully masked: nothing to do
        Ap = g_QKVh      + (long long)z * SEQ * DM3;     // Q slab
        Bp = g_QKVh + DM + (long long)z * SEQ * DM3;     // K slab
        Cp = g_P + (long long)z * SEQ * SEQ;
        lda = DM3; ldb = DM3; ldc = SEQ;
        mask = true; sc = 1.0f / 32.0f;
        gemm_body<128, true>(Ap, Bp, Cp, 16, lda, ldb, ldc, m0, n0, mask, false, sc);
    } else {
        const int id = (z - BATCH) * 256 + (int)blockIdx.y * 16 + (int)blockIdx.x; // 0..511
        m0 = (id >> 3) * 128;                   // 64 row blocks
        n0 = (id & 7) * 128;                    // 8 col blocks (DM=1024)
        Ap = g_Xh;
        Bp = g_Wh + 2 * DM * DM;                // Wv rows
        Cp = g_QKVh + 2 * DM;                   // V slab
        gemm_body<128, true>(Ap, Bp, Cp, 16, DM, DM, DM3, m0, n0, false, true, 1.0f);
    }
}

// 4) PV: ctx = P @ V  (NN, causal k-limit, half out, heavy-first)
__global__ __launch_bounds__(256, 2)
void pv_kernel()
{
    const int z = blockIdx.z;
    const int m0 = (int)(gridDim.y - 1 - blockIdx.y) * 128;
    const int n0 = (int)blockIdx.x * 128;
    const int ktiles = (m0 + 128) / 64;
    gemm_body<128, false>(g_Ph + (long long)z * SEQ * SEQ,
                          g_QKVh + 2 * DM + (long long)z * SEQ * DM3,
                          g_Ch + (long long)z * SEQ * DM,
                          ktiles, SEQ, DM3, DM, m0, n0, false, true, 1.0f);
}

// 5) o-proj split-K halves (z selects K half), fp32 partials into g_P scratch
__global__ __launch_bounds__(256, 2)
void oproj_kernel()
{
    const int z = blockIdx.z;
    float* op = g_P + (long long)z * MTOT * DVAL;
    gemm_body<64, true>(g_Ch + z * 512, g_Woh + z * 512, op,
                        8, DM, DM, DVAL,
                        (int)blockIdx.y * 128, 0, false, false, 1.0f);
}

// ---------------- fused fp32 -> fp16 pre-pass (single launch) ----------------
#define NX4  (MTOT * DM / 4)        // 2097152
#define NW4  (DM * DM / 4)          // 262144
#define NWO4 (DVAL * DM / 4)        // 16384
#define NALL4 (NX4 + 3 * NW4 + NWO4)

__global__ __launch_bounds__(256)
void f2h_all_kernel(const float4* __restrict__ x,  const float4* __restrict__ wq,
                    const float4* __restrict__ wk, const float4* __restrict__ wv,
                    const float4* __restrict__ wo)
{
    int i = blockIdx.x * 256 + threadIdx.x;
    const float4* src;
    __half2* dst;
    int off;
    if (i < NX4)                      { src = x;  dst = (__half2*)g_Xh;                 off = i; }
    else if (i < NX4 + NW4)           { src = wq; dst = (__half2*)g_Wh;                 off = i - NX4; }
    else if (i < NX4 + 2 * NW4)       { src = wk; dst = (__half2*)(g_Wh + DM * DM);     off = i - NX4 - NW4; }
    else if (i < NX4 + 3 * NW4)       { src = wv; dst = (__half2*)(g_Wh + 2 * DM * DM); off = i - NX4 - 2 * NW4; }
    else if (i < NALL4)               { src = wo; dst = (__half2*)g_Woh;                off = i - NX4 - 3 * NW4; }
    else return;
    float4 v = src[off];
    dst[2 * off]     = __floats2half2_rn(v.x, v.y);
    dst[2 * off + 1] = __floats2half2_rn(v.z, v.w);
}

// ---------------- split-K add: out = p0 + p1 (fp32) ----------------
__global__ __launch_bounds__(256)
void addk_kernel(const float4* __restrict__ p0, const float4* __restrict__ p1,
                 float4* __restrict__ out, int n4)
{
    int i = blockIdx.x * 256 + threadIdx.x;
    if (i < n4) {
        float4 a = p0[i], b = p1[i];
        out[i] = make_float4(a.x + b.x, a.y + b.y, a.z + b.z, a.w + b.w);
    }
}

// ---------------- causal softmax: warp-per-row, all-register ----------------
__global__ __launch_bounds__(256)
void softmax_kernel()
{
    const int gw   = blockIdx.x * 8 + (threadIdx.x >> 5);
    const int lane = threadIdx.x & 31;
    const long long row = MTOT - 1 - gw;          // heavy rows first
    const int r  = (int)(row & (SEQ - 1));
    const int C4 = ((r | 127) + 1) >> 2;
    const float4* p4 = (const float4*)(g_P + row * SEQ);
    __half2* o2 = (__half2*)(g_Ph + row * SEQ);

    float4 v[16];
    float m = __int_as_float(0xff800000);
    #pragma unroll
    for (int j = 0; j < 16; j++) {
        int i = lane + j * 32;
        if (i < C4) {
            v[j] = p4[i];
            m = fmaxf(m, fmaxf(fmaxf(v[j].x, v[j].y), fmaxf(v[j].z, v[j].w)));
        }
    }
    #pragma unroll
    for (int off = 16; off > 0; off >>= 1)
        m = fmaxf(m, __shfl_xor_sync(0xffffffffu, m, off));

    float sum = 0.0f;
    #pragma unroll
    for (int j = 0; j < 16; j++) {
        int i = lane + j * 32;
        if (i < C4) {
            v[j].x = __expf(v[j].x - m); v[j].y = __expf(v[j].y - m);
            v[j].z = __expf(v[j].z - m); v[j].w = __expf(v[j].w - m);
            sum += (v[j].x + v[j].y) + (v[j].z + v[j].w);
        }
    }
    #pragma unroll
    for (int off = 16; off > 0; off >>= 1)
        sum += __shfl_xor_sync(0xffffffffu, sum, off);
    const float inv = 1.0f / sum;

    #pragma unroll
    for (int j = 0; j < 16; j++) {
        int i = lane + j * 32;
        if (i < C4) {
            o2[2 * i]     = __floats2half2_rn(v[j].x * inv, v[j].y * inv);
            o2[2 * i + 1] = __floats2half2_rn(v[j].z * inv, v[j].w * inv);
        }
    }
}

// ---------------- host ----------------
extern "C" void kernel_launch(void* const* d_in, const int* in_sizes, int n_in,
                              void* d_out, int out_size)
{
    const float* x  = (const float*)d_in[0];
    const float* Wq = (const float*)d_in[1];
    const float* Wk = (const float*)d_in[2];
    const float* Wv = (const float*)d_in[3];
    const float* Wo = (const float*)d_in[4];
    float* out = (float*)d_out;

    float* P;
    cudaGetSymbolAddress((void**)&P, g_P);
    float* op0 = P;
    float* op1 = P + (size_t)MTOT * DVAL;

    const int smNT128 = 3 * (16384 + 128 * 128);    // 96KB
    const int smNN128 = 3 * (16384 + 64 * 128 * 2); // 96KB
    const int smNT64  = 3 * (16384 + 64 * 128);     // 72KB
    cudaFuncSetAttribute(qk_kernel,       cudaFuncAttributeMaxDynamicSharedMemorySize, smNT128);
    cudaFuncSetAttribute(scores_v_kernel, cudaFuncAttributeMaxDynamicSharedMemorySize, smNT128);
    cudaFuncSetAttribute(pv_kernel,       cudaFuncAttributeMaxDynamicSharedMemorySize, smNN128);
    cudaFuncSetAttribute(oproj_kernel,    cudaFuncAttributeMaxDynamicSharedMemorySize, smNT64);

    const dim3 blk(256);

    // 0) fused fp32->fp16 prepass
    f2h_all_kernel<<<(NALL4 + 255) / 256, 256>>>(
        (const float4*)x, (const float4*)Wq, (const float4*)Wk,
        (const float4*)Wv, (const float4*)Wo);

    // 1) QK projection: [8192, 2048]
    qk_kernel<<<dim3(2048 / 128, MTOT / 128, 1), blk, smNT128>>>();

    // 2) fused causal scores + V projection (one launch, work-stealing overlap)
    scores_v_kernel<<<dim3(16, 16, BATCH + 2), blk, smNT128>>>();

    // 3) causal softmax: fp32 scores -> fp16 probs
    softmax_kernel<<<MTOT / 8, 256>>>();

    // 4) ctx = P @ V
    pv_kernel<<<dim3(DM / 128, SEQ / 128, BATCH), blk, smNN128>>>();

    // 5) out = ctx @ Wo^T, 2-way split-K + add
    oproj_kernel<<<dim3(1, MTOT / 128, 2), blk, smNT64>>>();
    addk_kernel<<<(MTOT * DVAL / 4 + 255) / 256, 256>>>(
        (const float4*)op0, (const float4*)op1, (float4*)out, MTOT * DVAL / 4);
}